// round 8
// baseline (speedup 1.0000x reference)
#include <cuda_runtime.h>
#include <cstdint>

// Gegenbauer (alpha=0.5 -> Legendre) embedding: out[row, i-1] = C_i(x[row]), i=1..64.
// Round 8: 256-bit global stores (st.global.v8.b32, sm_100+) in the copy-out:
// 8 STG per thread instead of 16, each warp instruction = 1024B contiguous.
// Two 32-column passes through padded smem (PAD=9 f4), conflict-free STS/LDS.

#define DIM_OUT 64
#define RPB 128          // rows per block == threads
#define HF4 8            // float4 per half-row (32 floats = 128B)
#define PAD 9            // smem row stride in float4

__device__ __forceinline__ void stg256(float* p, float4 a, float4 b) {
    asm volatile(
        "st.global.v8.b32 [%0], {%1,%2,%3,%4,%5,%6,%7,%8};"
        :: "l"(p),
           "r"(__float_as_uint(a.x)), "r"(__float_as_uint(a.y)),
           "r"(__float_as_uint(a.z)), "r"(__float_as_uint(a.w)),
           "r"(__float_as_uint(b.x)), "r"(__float_as_uint(b.y)),
           "r"(__float_as_uint(b.z)), "r"(__float_as_uint(b.w))
        : "memory");
}

template <bool FULL>
__global__ void __launch_bounds__(RPB) geg_kernel(const float* __restrict__ x,
                                                  float* __restrict__ out,
                                                  int n) {
    __shared__ float4 s[RPB * PAD];   // 18,432 B

    const int tid = threadIdx.x;
    const size_t row = (size_t)blockIdx.x * RPB + tid;
    const float xv = FULL ? x[row] : ((row < (size_t)n) ? x[row] : 0.0f);

    const size_t base_f = (size_t)blockIdx.x * RPB * DIM_OUT;   // float index of tile
    const size_t total_f4 = ((size_t)n * DIM_OUT) / 4;
    float4* __restrict__ o4 = reinterpret_cast<float4*>(out);

    float prev2 = 1.0f;   // C_0
    float prev  = xv;     // C_1 (alpha = 0.5)

    #pragma unroll
    for (int pass = 0; pass < 2; ++pass) {
        // ---- compute 32 coefficients, streaming to smem 4 at a time ----
        #pragma unroll
        for (int g = 0; g < HF4; ++g) {
            float4 v;
            float* vp = reinterpret_cast<float*>(&v);
            #pragma unroll
            for (int e = 0; e < 4; ++e) {
                const int k = pass * 32 + g * 4 + e;   // slot holds C_{k+1}
                float ci;
                if (k == 0) {
                    ci = xv;                            // C_1
                } else {
                    const int i = k + 1;
                    const float A = (float)(2 * i - 1);
                    const float B = (float)(1 - i);
                    const float r = 1.0f / (float)i;
                    ci = (A * xv * prev + B * prev2) * r;
                    prev2 = prev;
                    prev  = ci;
                }
                vp[e] = ci;
            }
            s[tid * PAD + g] = v;   // conflict-free: (9*tid+g)%8 distinct per phase
        }
        __syncthreads();

        if (FULL) {
            // ---- copy-out in 32B (float8) units: 4 x STG.256 per thread ----
            // Tile this pass: 128 rows x 8 f4 = 512 f8-chunks; 128 threads x 4.
            #pragma unroll
            for (int j = 0; j < 4; ++j) {
                const int h = j * RPB + tid;   // f8 index within tile
                const int r = h >> 2;          // row within block
                const int c2 = h & 3;          // f8 column within half-row
                const float4 a = s[r * PAD + 2 * c2];
                const float4 b = s[r * PAD + 2 * c2 + 1];
                float* dst = out + base_f + (size_t)r * DIM_OUT
                           + (size_t)pass * 32 + (size_t)c2 * 8;
                stg256(dst, a, b);
            }
        } else {
            // Guarded fallback (n not multiple of RPB): float4 stores.
            const size_t base_f4 = base_f / 4;
            #pragma unroll
            for (int j = 0; j < HF4; ++j) {
                const int f = j * RPB + tid;
                const int r = f >> 3;
                const int cq = f & 7;
                const size_t g = base_f4 + (size_t)r * (DIM_OUT / 4) + pass * HF4 + cq;
                if (g < total_f4) o4[g] = s[r * PAD + cq];
            }
        }
        if (pass == 0) __syncthreads();   // guard smem reuse
    }
}

extern "C" void kernel_launch(void* const* d_in, const int* in_sizes, int n_in,
                              void* d_out, int out_size) {
    const float* x = (const float*)d_in[0];
    float* out = (float*)d_out;
    int n = in_sizes[0];   // 2,000,000 rows = 15625 full tiles of 128
    int blocks = (n + RPB - 1) / RPB;
    if (n % RPB == 0) {
        geg_kernel<true><<<blocks, RPB>>>(x, out, n);
    } else {
        geg_kernel<false><<<blocks, RPB>>>(x, out, n);
    }
}

// round 9
// speedup vs baseline: 1.0200x; 1.0200x over previous
#include <cuda_runtime.h>

// Gegenbauer (alpha=0.5 -> Legendre) embedding: out[row, i-1] = C_i(x[row]), i=1..64.
// Final form (converged at the HBM3e write wall, ~6.5 TB/s effective):
//  - one thread per row, recurrence fully unrolled (constants fold to immediates)
//  - two 32-column passes through padded smem (PAD=9 f4, conflict-free STS/LDS)
//  - register-buffered compute then tight STS burst (best-measured variant)
//  - unguarded full-tile copy-out (n = 128*15625 exactly), coalesced 128B lines
//  - pass-1 compute overlaps pass-0 stores in flight; no trailing barrier

#define DIM_OUT 64
#define RPB 128          // rows per block == threads
#define HF4 8            // float4 per half-row (32 floats = 128B)
#define PAD 9            // smem row stride in float4

template <bool FULL>
__global__ void __launch_bounds__(RPB) geg_kernel(const float* __restrict__ x,
                                                  float* __restrict__ out,
                                                  int n) {
    __shared__ float4 s[RPB * PAD];   // 18,432 B

    const int tid = threadIdx.x;
    const size_t row = (size_t)blockIdx.x * RPB + tid;
    const float xv = FULL ? x[row] : ((row < (size_t)n) ? x[row] : 0.0f);

    float4* __restrict__ o4 = reinterpret_cast<float4*>(out);
    const size_t base_f4 = (size_t)blockIdx.x * RPB * (DIM_OUT / 4);
    const size_t total_f4 = ((size_t)n * DIM_OUT) / 4;

    float c[32];
    float prev2 = 1.0f;   // C_0
    float prev  = xv;     // C_1 (alpha = 0.5)
    c[0] = xv;

    // ---- Pass 0: compute C_1..C_32 into registers ----
    // C_i = ((2i-1)*x*C_{i-1} + (1-i)*C_{i-2}) * (1/i)
    #pragma unroll
    for (int i = 2; i <= 32; ++i) {
        const float A = (float)(2 * i - 1);
        const float B = (float)(1 - i);
        const float r = 1.0f / (float)i;
        const float ci = (A * xv * prev + B * prev2) * r;
        c[i - 1] = ci;
        prev2 = prev;
        prev  = ci;
    }

    #pragma unroll
    for (int j = 0; j < HF4; ++j)
        s[tid * PAD + j] = make_float4(c[4*j], c[4*j+1], c[4*j+2], c[4*j+3]);
    __syncthreads();

    // Coalesced copy-out of column block 0 (cols 0..31 of each row).
    #pragma unroll
    for (int j = 0; j < HF4; ++j) {
        const int f = j * RPB + tid;       // index within 128x8 f4 tile
        const int r = f >> 3;              // row within block
        const int cq = f & 7;              // f4 column within half-row
        const size_t g = base_f4 + (size_t)r * (DIM_OUT / 4) + cq;
        if (FULL) {
            o4[g] = s[r * PAD + cq];
        } else if (g < total_f4) {
            o4[g] = s[r * PAD + cq];
        }
    }
    __syncthreads();

    // ---- Pass 1: compute C_33..C_64 (overlaps pass-0 stores in flight) ----
    #pragma unroll
    for (int i = 33; i <= DIM_OUT; ++i) {
        const float A = (float)(2 * i - 1);
        const float B = (float)(1 - i);
        const float r = 1.0f / (float)i;
        const float ci = (A * xv * prev + B * prev2) * r;
        c[i - 33] = ci;
        prev2 = prev;
        prev  = ci;
    }

    #pragma unroll
    for (int j = 0; j < HF4; ++j)
        s[tid * PAD + j] = make_float4(c[4*j], c[4*j+1], c[4*j+2], c[4*j+3]);
    __syncthreads();

    // Coalesced copy-out of column block 1 (cols 32..63 of each row).
    #pragma unroll
    for (int j = 0; j < HF4; ++j) {
        const int f = j * RPB + tid;
        const int r = f >> 3;
        const int cq = f & 7;
        const size_t g = base_f4 + (size_t)r * (DIM_OUT / 4) + HF4 + cq;
        if (FULL) {
            o4[g] = s[r * PAD + cq];
        } else if (g < total_f4) {
            o4[g] = s[r * PAD + cq];
        }
    }
    // no trailing barrier: kernel exit synchronizes
}

extern "C" void kernel_launch(void* const* d_in, const int* in_sizes, int n_in,
                              void* d_out, int out_size) {
    const float* x = (const float*)d_in[0];
    float* out = (float*)d_out;
    int n = in_sizes[0];   // 2,000,000 rows = 15625 full tiles of 128
    int blocks = (n + RPB - 1) / RPB;
    if (n % RPB == 0) {
        geg_kernel<true><<<blocks, RPB>>>(x, out, n);
    } else {
        geg_kernel<false><<<blocks, RPB>>>(x, out, n);
    }
}